// round 12
// baseline (speedup 1.0000x reference)
#include <cuda_runtime.h>
#include <cuda_fp16.h>
#include <cstdint>
#include <cstddef>

#define T_STEPS 14
#define BSZ     8192
#define EMBED   256
#define HIDDEN  512
#define VOCAB   193
#define SEQLEN  15
#define GW      1536          // 3*HIDDEN

// fp16 GEMM tiling: BK = 64 halves per k-tile; row = 32 u32 (128 B) + pad
#define PITCH   36            // smem row pitch in u32 -> conflict-free frags
#define ATILE   (128 * PITCH) // one 128x64(half) tile in u32
#define NSTAGE  3
#define GEMM_SMEM (NSTAGE * 2 * ATILE * 4)   // 110592 B

// ---------------- scratch (device globals) ----------------------------------
__device__ int    g_is64;
__device__ int    g_tok[T_STEPS * BSZ];
__device__ float  g_G   [(size_t)VOCAB * GW];                  // gi lookup (fp32)
__device__ float  g_gh  [(size_t)BSZ * GW];                    // 50 MB
__device__ float  g_h0  [(size_t)BSZ * HIDDEN];                // fp32 h0
__device__ __half g_h0h [(size_t)BSZ * HIDDEN];                // fp16 h0
__device__ float  g_hs  [(size_t)T_STEPS * BSZ * HIDDEN];      // fp32 states
__device__ __half g_hsh [(size_t)T_STEPS * BSZ * HIDDEN];      // fp16 states
__device__ __half g_imgh [(size_t)BSZ * 512];
__device__ __half g_Wprojh[(size_t)HIDDEN * 512];
__device__ __half g_Whhh [(size_t)GW * HIDDEN];
__device__ __half g_Wouth[(size_t)VOCAB * HIDDEN];

// ---------------- mma / cp.async helpers ------------------------------------
__device__ __forceinline__ void mma_f16(float c[4], const uint32_t a[4],
                                        const uint32_t b[2]) {
    asm volatile(
        "mma.sync.aligned.m16n8k16.row.col.f32.f16.f16.f32 "
        "{%0,%1,%2,%3}, {%4,%5,%6,%7}, {%8,%9}, {%0,%1,%2,%3};"
        : "+f"(c[0]), "+f"(c[1]), "+f"(c[2]), "+f"(c[3])
        : "r"(a[0]), "r"(a[1]), "r"(a[2]), "r"(a[3]), "r"(b[0]), "r"(b[1]));
}
__device__ __forceinline__ void cpa16(uint32_t d, const void* s) {
    asm volatile("cp.async.cg.shared.global [%0], [%1], 16;" :: "r"(d), "l"(s));
}
__device__ __forceinline__ void cp_commit() {
    asm volatile("cp.async.commit_group;");
}
template <int N> __device__ __forceinline__ void cp_wait() {
    asm volatile("cp.async.wait_group %0;" :: "n"(N));
}

// ---------------- token dtype detect + normalize ----------------------------
// int64 text (little-endian): every odd 32-bit word is 0 (tokens < 193).
__global__ void detect_dtype_kernel(const int* __restrict__ text_words) {
    __shared__ int nz;
    if (threadIdx.x == 0) nz = 0;
    __syncthreads();
    for (int i = threadIdx.x; i < 2048; i += blockDim.x)
        if (text_words[2 * i + 1] != 0) atomicOr(&nz, 1);
    __syncthreads();
    if (threadIdx.x == 0) g_is64 = nz ? 0 : 1;
}

__global__ void convert_tok_kernel(const void* __restrict__ text) {
    int i = blockIdx.x * blockDim.x + threadIdx.x;     // i = b*14 + t
    if (i >= T_STEPS * BSZ) return;
    int b = i / T_STEPS, t = i - b * T_STEPS;
    int src = b * SEQLEN + t;
    int v;
    if (g_is64) v = (int)((const long long*)text)[src];
    else        v = ((const int*)text)[src];
    g_tok[i] = v;
}

// ---------------- elementwise fp32 -> fp16 conversion ------------------------
__global__ void cvt_h_kernel(const float* __restrict__ src,
                             __half* __restrict__ dst, int n) {
    int i = blockIdx.x * blockDim.x + threadIdx.x;
    if (i < n) dst[i] = __float2half_rn(src[i]);
}

// ---------------- G table: G[v][n] = emb[v].W_ih[n] + b_ih[n] (fp32) --------
__global__ void build_G_kernel(const float* __restrict__ emb,
                               const float* __restrict__ W_ih,
                               const float* __restrict__ b_ih) {
    int idx = blockIdx.x * blockDim.x + threadIdx.x;
    if (idx >= VOCAB * GW) return;
    int v = idx / GW, n = idx - v * GW;
    const float* er = emb  + (size_t)v * EMBED;
    const float* wr = W_ih + (size_t)n * EMBED;
    float s = b_ih[n];
#pragma unroll 8
    for (int k = 0; k < EMBED; k++) s += er[k] * wr[k];
    g_G[idx] = s;
}

// ---------------- 3-stage pipelined fp16 NT GEMM -----------------------------
// C[M,N] = A[M,K] @ B[N,K]^T + bias.  A,B fp16. K%64==0, M%128==0.
// mode 0: C[m*ldc+n] fp32 (+ optional fp16 copy Ch). mode 1: preds remap.
__global__ __launch_bounds__(256, 2) void gemm_f16_p3(
    const __half* __restrict__ A, const __half* __restrict__ Bm,
    const float* __restrict__ bias, float* __restrict__ C,
    __half* __restrict__ Ch,
    int M, int N, int K, int ldc, int mode)
{
    extern __shared__ uint32_t sm[];
    uint32_t* As = sm;                       // [NSTAGE][ATILE]
    uint32_t* Bs = sm + NSTAGE * ATILE;      // [NSTAGE][ATILE]
    uint32_t as_u = (uint32_t)__cvta_generic_to_shared(As);
    uint32_t bs_u = (uint32_t)__cvta_generic_to_shared(Bs);

    const int tid = threadIdx.x, lane = tid & 31, warp = tid >> 5;
    const int g = lane >> 2, t4 = lane & 3;
    const int m0 = blockIdx.y * 128, n0 = blockIdx.x * 128;
    const int wm0 = (warp >> 2) * 64, wn0 = (warp & 3) * 32;

    float acc[4][4][4];
#pragma unroll
    for (int mf = 0; mf < 4; mf++)
#pragma unroll
        for (int nf = 0; nf < 4; nf++)
#pragma unroll
            for (int e = 0; e < 4; e++) acc[mf][nf][e] = 0.f;

    // one tile = 128 rows x 64 halves (= 32 u32 = 8 x 16B chunks per row)
    auto load_tiles = [&](int k0, int buf) {
#pragma unroll
        for (int it = 0; it < 4; it++) {
            int idx = tid + it * 256;          // 0..1023
            int r = idx >> 3, c4 = idx & 7;    // row, 16B chunk (8 halves)
            cpa16(as_u + (uint32_t)(buf * ATILE + r * PITCH + c4 * 4) * 4,
                  A + (size_t)(m0 + r) * K + k0 + c4 * 8);
            int gn = n0 + r;
            if (gn < N) {
                cpa16(bs_u + (uint32_t)(buf * ATILE + r * PITCH + c4 * 4) * 4,
                      Bm + (size_t)gn * K + k0 + c4 * 8);
            } else {
                uint4 z = make_uint4(0u, 0u, 0u, 0u);
                *reinterpret_cast<uint4*>(&Bs[buf * ATILE + r * PITCH + c4 * 4]) = z;
            }
        }
    };

    // prologue: stages 0,1 in flight
    load_tiles(0, 0);  cp_commit();
    if (64 < K) load_tiles(64, 1);
    cp_commit();

    int buf = 0;
    for (int k0 = 0; k0 < K; k0 += 64) {
        cp_wait<1>();        // tile for k0 retired (FIFO; 1 group may stay in flight)
        __syncthreads();     // cross-thread visibility + WAR protection
        const uint32_t* Ab = As + buf * ATILE;
        const uint32_t* Bb = Bs + buf * ATILE;
#pragma unroll
        for (int ks = 0; ks < 4; ks++) {       // each ks = 16 halves = 8 u32
            // fp16 m16n8k16 A frag (u32 = 2 halves):
            //   a0=(row g, k 2t4..+1)  a1=(g+8, same)  a2=(g, k 8+2t4..)  a3=(g+8,..)
            uint32_t afr[4][4];
#pragma unroll
            for (int mf = 0; mf < 4; mf++) {
                const uint32_t* p = Ab + (wm0 + mf * 16 + g) * PITCH + ks * 8 + t4;
                afr[mf][0] = p[0];
                afr[mf][1] = p[8 * PITCH];
                afr[mf][2] = p[4];
                afr[mf][3] = p[8 * PITCH + 4];
            }
            // B frag: b0=(n g, k 2t4..+1)  b1=(n g, k 8+2t4..)
            uint32_t bfr[4][2];
#pragma unroll
            for (int nf = 0; nf < 4; nf++) {
                const uint32_t* p = Bb + (wn0 + nf * 8 + g) * PITCH + ks * 8 + t4;
                bfr[nf][0] = p[0];
                bfr[nf][1] = p[4];
            }
#pragma unroll
            for (int mf = 0; mf < 4; mf++)
#pragma unroll
                for (int nf = 0; nf < 4; nf++)
                    mma_f16(acc[mf][nf], afr[mf], bfr[nf]);
        }
        // prefetch k0+128 into the buffer read last iteration (safe: the
        // __syncthreads above separated those reads from these writes)
        if (k0 + 128 < K) load_tiles(k0 + 128, (buf + 2) % NSTAGE);
        cp_commit();         // commit every iter (possibly empty) keeps FIFO math
        buf = (buf + 1) % NSTAGE;
    }

    // ---- epilogue ----
#pragma unroll
    for (int mf = 0; mf < 4; mf++) {
#pragma unroll
        for (int nf = 0; nf < 4; nf++) {
            int nbase = n0 + wn0 + nf * 8 + t4 * 2;
            float bias0 = 0.f, bias1 = 0.f;
            if (bias) {
                if (nbase < N)     bias0 = bias[nbase];
                if (nbase + 1 < N) bias1 = bias[nbase + 1];
            }
#pragma unroll
            for (int e = 0; e < 4; e++) {
                int m = m0 + wm0 + mf * 16 + g + ((e >= 2) ? 8 : 0);
                int n = nbase + (e & 1);
                if (n >= N) continue;
                float v = acc[mf][nf][e] + ((e & 1) ? bias1 : bias0);
                if (mode == 0) {
                    C[(size_t)m * ldc + n] = v;
                    if (Ch) Ch[(size_t)m * ldc + n] = __float2half_rn(v);
                } else {
                    int t = m >> 13, b = m & (BSZ - 1);
                    C[((size_t)b * T_STEPS + t) * VOCAB + n] = v;
                }
            }
        }
    }
}

// ---------------- gate kernel: h_t = GRU(G[tok], gh, h_prev), dual write ----
__global__ __launch_bounds__(256) void gate_kernel(int t)
{
    int idx = blockIdx.x * blockDim.x + threadIdx.x;   // one per 4 elems
    if (idx >= BSZ * (HIDDEN / 4)) return;
    int m = idx >> 7;            // HIDDEN/4 = 128
    int n = (idx & 127) * 4;

    const float* hp = (t == 0) ? g_h0 : (g_hs + (size_t)(t - 1) * BSZ * HIDDEN);
    float*  hout  = g_hs  + (size_t)t * BSZ * HIDDEN;
    __half* houth = g_hsh + (size_t)t * BSZ * HIDDEN;
    int tok = g_tok[m * T_STEPS + t];

    const float* Gr = g_G  + (size_t)tok * GW;
    const float* gh = g_gh + (size_t)m * GW;

    float4 gir = *reinterpret_cast<const float4*>(&Gr[n]);
    float4 giz = *reinterpret_cast<const float4*>(&Gr[HIDDEN + n]);
    float4 gin = *reinterpret_cast<const float4*>(&Gr[2 * HIDDEN + n]);
    float4 ghr = *reinterpret_cast<const float4*>(&gh[n]);
    float4 ghz = *reinterpret_cast<const float4*>(&gh[HIDDEN + n]);
    float4 ghn = *reinterpret_cast<const float4*>(&gh[2 * HIDDEN + n]);
    float4 hv  = *reinterpret_cast<const float4*>(&hp[(size_t)m * HIDDEN + n]);

    float4 o;
    {
        float r = 1.f / (1.f + expf(-(gir.x + ghr.x)));
        float z = 1.f / (1.f + expf(-(giz.x + ghz.x)));
        float nn = tanhf(gin.x + r * ghn.x);
        o.x = (1.f - z) * nn + z * hv.x;
    }
    {
        float r = 1.f / (1.f + expf(-(gir.y + ghr.y)));
        float z = 1.f / (1.f + expf(-(giz.y + ghz.y)));
        float nn = tanhf(gin.y + r * ghn.y);
        o.y = (1.f - z) * nn + z * hv.y;
    }
    {
        float r = 1.f / (1.f + expf(-(gir.z + ghr.z)));
        float z = 1.f / (1.f + expf(-(giz.z + ghz.z)));
        float nn = tanhf(gin.z + r * ghn.z);
        o.z = (1.f - z) * nn + z * hv.z;
    }
    {
        float r = 1.f / (1.f + expf(-(gir.w + ghr.w)));
        float z = 1.f / (1.f + expf(-(giz.w + ghz.w)));
        float nn = tanhf(gin.w + r * ghn.w);
        o.w = (1.f - z) * nn + z * hv.w;
    }
    *reinterpret_cast<float4*>(&hout[(size_t)m * HIDDEN + n]) = o;
    __half2 p0 = __floats2half2_rn(o.x, o.y);
    __half2 p1 = __floats2half2_rn(o.z, o.w);
    *reinterpret_cast<__half2*>(&houth[(size_t)m * HIDDEN + n])     = p0;
    *reinterpret_cast<__half2*>(&houth[(size_t)m * HIDDEN + n + 2]) = p1;
}

// ---------------- launch ----------------
extern "C" void kernel_launch(void* const* d_in, const int* in_sizes, int n_in,
                              void* d_out, int out_size)
{
    const float* img    = (const float*)d_in[0];
    const void*  text   = d_in[1];
    const float* emb    = (const float*)d_in[2];
    const float* W_proj = (const float*)d_in[3];
    const float* b_proj = (const float*)d_in[4];
    const float* W_ih   = (const float*)d_in[5];
    const float* W_hh   = (const float*)d_in[6];
    const float* b_ih   = (const float*)d_in[7];
    const float* b_hh   = (const float*)d_in[8];
    const float* W_out  = (const float*)d_in[9];
    const float* b_out  = (const float*)d_in[10];
    float* out = (float*)d_out;

    cudaFuncSetAttribute(gemm_f16_p3,
        cudaFuncAttributeMaxDynamicSharedMemorySize, GEMM_SMEM);

    float  *ph0, *phs, *pgh;
    __half *ph0h, *phsh, *pimgh, *pWprojh, *pWhhh, *pWouth;
    cudaGetSymbolAddress((void**)&ph0,   g_h0);
    cudaGetSymbolAddress((void**)&ph0h,  g_h0h);
    cudaGetSymbolAddress((void**)&phs,   g_hs);
    cudaGetSymbolAddress((void**)&phsh,  g_hsh);
    cudaGetSymbolAddress((void**)&pgh,   g_gh);
    cudaGetSymbolAddress((void**)&pimgh, g_imgh);
    cudaGetSymbolAddress((void**)&pWprojh, g_Wprojh);
    cudaGetSymbolAddress((void**)&pWhhh,   g_Whhh);
    cudaGetSymbolAddress((void**)&pWouth,  g_Wouth);

    // 1) tokens
    detect_dtype_kernel<<<1, 256>>>((const int*)text);
    convert_tok_kernel<<<(T_STEPS * BSZ + 255) / 256, 256>>>(text);

    // 2) pre-convert GEMM operands to fp16 (once)
    cvt_h_kernel<<<(BSZ * 512 + 255) / 256, 256>>>(img, pimgh, BSZ * 512);
    cvt_h_kernel<<<(HIDDEN * 512 + 255) / 256, 256>>>(W_proj, pWprojh, HIDDEN * 512);
    cvt_h_kernel<<<(GW * HIDDEN + 255) / 256, 256>>>(W_hh, pWhhh, GW * HIDDEN);
    cvt_h_kernel<<<(VOCAB * HIDDEN + 255) / 256, 256>>>(W_out, pWouth, VOCAB * HIDDEN);

    // 3) G lookup table (replaces the entire input-projection GEMM)
    build_G_kernel<<<(VOCAB * GW + 255) / 256, 256>>>(emb, W_ih, b_ih);

    // 4) h0 = img @ W_proj^T + b_proj  (writes fp32 + fp16 copies)
    gemm_f16_p3<<<dim3(HIDDEN / 128, BSZ / 128), 256, GEMM_SMEM>>>(
        pimgh, pWprojh, b_proj, ph0, ph0h, BSZ, HIDDEN, 512, HIDDEN, 0);

    // 5) 14 GRU steps: gh GEMM (fp16 tensor) + gate elementwise
    for (int t = 0; t < T_STEPS; t++) {
        const __half* hph = (t == 0) ? ph0h : (phsh + (size_t)(t - 1) * BSZ * HIDDEN);
        gemm_f16_p3<<<dim3(GW / 128, BSZ / 128), 256, GEMM_SMEM>>>(
            hph, pWhhh, b_hh, pgh, nullptr, BSZ, GW, HIDDEN, GW, 0);
        gate_kernel<<<(BSZ * (HIDDEN / 4) + 255) / 256, 256>>>(t);
    }

    // 6) preds = hs @ W_out^T + b_out, remapped to [B, T, V]
    gemm_f16_p3<<<dim3(2, (T_STEPS * BSZ) / 128), 256, GEMM_SMEM>>>(
        phsh, pWouth, b_out, out, nullptr, T_STEPS * BSZ, VOCAB, HIDDEN, VOCAB, 1);
}

// round 14
// speedup vs baseline: 1.0099x; 1.0099x over previous
#include <cuda_runtime.h>
#include <cuda_fp16.h>
#include <cstdint>
#include <cstddef>

#define T_STEPS 14
#define BSZ     8192
#define EMBED   256
#define HIDDEN  512
#define VOCAB   193
#define SEQLEN  15
#define GW      1536          // 3*HIDDEN

// ---- shared tiling constants ----
#define PITCH   36            // smem row pitch in u32 -> conflict-free frags
#define NSTAGE  3
// 128x128 kernel (h0/preds)
#define ATILE   (128 * PITCH)
#define GEMM_SMEM (NSTAGE * 2 * ATILE * 4)          // 110592 B
// 256x128 kernel (gh)
#define ATILE_B (256 * PITCH)
#define BTILE_B (128 * PITCH)
#define BIG_SMEM (NSTAGE * (ATILE_B + BTILE_B) * 4) // 165888 B

// ---------------- scratch (device globals) ----------------------------------
__device__ int    g_is64;
__device__ int    g_tok[T_STEPS * BSZ];
__device__ float  g_G   [(size_t)VOCAB * GW];                  // gi lookup (fp32)
__device__ float  g_gh  [(size_t)BSZ * GW];                    // 50 MB
__device__ float  g_h0  [(size_t)BSZ * HIDDEN];                // fp32 h0
__device__ __half g_h0h [(size_t)BSZ * HIDDEN];                // fp16 h0
__device__ float  g_hs  [(size_t)T_STEPS * BSZ * HIDDEN];      // fp32 states
__device__ __half g_hsh [(size_t)T_STEPS * BSZ * HIDDEN];      // fp16 states
__device__ __half g_imgh [(size_t)BSZ * 512];
__device__ __half g_Wprojh[(size_t)HIDDEN * 512];
__device__ __half g_Whhh [(size_t)GW * HIDDEN];
__device__ __half g_Wouth[(size_t)VOCAB * HIDDEN];

// ---------------- mma / cp.async helpers ------------------------------------
__device__ __forceinline__ void mma_f16(float c[4], const uint32_t a[4],
                                        const uint32_t b[2]) {
    asm volatile(
        "mma.sync.aligned.m16n8k16.row.col.f32.f16.f16.f32 "
        "{%0,%1,%2,%3}, {%4,%5,%6,%7}, {%8,%9}, {%0,%1,%2,%3};"
        : "+f"(c[0]), "+f"(c[1]), "+f"(c[2]), "+f"(c[3])
        : "r"(a[0]), "r"(a[1]), "r"(a[2]), "r"(a[3]), "r"(b[0]), "r"(b[1]));
}
__device__ __forceinline__ void cpa16(uint32_t d, const void* s) {
    asm volatile("cp.async.cg.shared.global [%0], [%1], 16;" :: "r"(d), "l"(s));
}
__device__ __forceinline__ void cp_commit() {
    asm volatile("cp.async.commit_group;");
}
template <int N> __device__ __forceinline__ void cp_wait() {
    asm volatile("cp.async.wait_group %0;" :: "n"(N));
}

// ---------------- token dtype detect + normalize ----------------------------
// int64 text (little-endian): every odd 32-bit word is 0 (tokens < 193).
__global__ void detect_dtype_kernel(const int* __restrict__ text_words) {
    __shared__ int nz;
    if (threadIdx.x == 0) nz = 0;
    __syncthreads();
    for (int i = threadIdx.x; i < 2048; i += blockDim.x)
        if (text_words[2 * i + 1] != 0) atomicOr(&nz, 1);
    __syncthreads();
    if (threadIdx.x == 0) g_is64 = nz ? 0 : 1;
}

__global__ void convert_tok_kernel(const void* __restrict__ text) {
    int i = blockIdx.x * blockDim.x + threadIdx.x;     // i = b*14 + t
    if (i >= T_STEPS * BSZ) return;
    int b = i / T_STEPS, t = i - b * T_STEPS;
    int src = b * SEQLEN + t;
    int v;
    if (g_is64) v = (int)((const long long*)text)[src];
    else        v = ((const int*)text)[src];
    g_tok[i] = v;
}

// ---------------- elementwise fp32 -> fp16 conversion ------------------------
__global__ void cvt_h_kernel(const float* __restrict__ src,
                             __half* __restrict__ dst, int n) {
    int i = blockIdx.x * blockDim.x + threadIdx.x;
    if (i < n) dst[i] = __float2half_rn(src[i]);
}

// ---------------- G table: G[v][n] = emb[v].W_ih[n] + b_ih[n] (fp32) --------
__global__ void build_G_kernel(const float* __restrict__ emb,
                               const float* __restrict__ W_ih,
                               const float* __restrict__ b_ih) {
    int idx = blockIdx.x * blockDim.x + threadIdx.x;
    if (idx >= VOCAB * GW) return;
    int v = idx / GW, n = idx - v * GW;
    const float* er = emb  + (size_t)v * EMBED;
    const float* wr = W_ih + (size_t)n * EMBED;
    float s = b_ih[n];
#pragma unroll 8
    for (int k = 0; k < EMBED; k++) s += er[k] * wr[k];
    g_G[idx] = s;
}

// ---------------- 256x128 fp16 NT GEMM (gh): max MMA density ----------------
// C[M,N] = A[M,K] @ B[N,K]^T + bias. M%256==0, K%64==0, N%128==0 for this path.
__global__ __launch_bounds__(256, 1) void gemm_f16_big(
    const __half* __restrict__ A, const __half* __restrict__ Bm,
    const float* __restrict__ bias, float* __restrict__ C,
    int M, int N, int K, int ldc)
{
    extern __shared__ uint32_t sm[];
    uint32_t* As = sm;                        // [NSTAGE][ATILE_B]
    uint32_t* Bs = sm + NSTAGE * ATILE_B;     // [NSTAGE][BTILE_B]
    uint32_t as_u = (uint32_t)__cvta_generic_to_shared(As);
    uint32_t bs_u = (uint32_t)__cvta_generic_to_shared(Bs);

    const int tid = threadIdx.x, lane = tid & 31, warp = tid >> 5;
    const int g = lane >> 2, t4 = lane & 3;
    const int m0 = blockIdx.y * 256, n0 = blockIdx.x * 128;
    const int wm0 = (warp >> 1) * 64, wn0 = (warp & 1) * 64;   // warp: 64m x 64n

    float acc[4][8][4];                       // 128 regs
#pragma unroll
    for (int mf = 0; mf < 4; mf++)
#pragma unroll
        for (int nf = 0; nf < 8; nf++)
#pragma unroll
            for (int e = 0; e < 4; e++) acc[mf][nf][e] = 0.f;

    auto load_tiles = [&](int k0, int buf) {
#pragma unroll
        for (int it = 0; it < 8; it++) {       // A: 256 rows x 8 chunks
            int idx = tid + it * 256;          // 0..2047
            int r = idx >> 3, c4 = idx & 7;
            cpa16(as_u + (uint32_t)(buf * ATILE_B + r * PITCH + c4 * 4) * 4,
                  A + (size_t)(m0 + r) * K + k0 + c4 * 8);
        }
#pragma unroll
        for (int it = 0; it < 4; it++) {       // B: 128 rows x 8 chunks
            int idx = tid + it * 256;          // 0..1023
            int r = idx >> 3, c4 = idx & 7;
            cpa16(bs_u + (uint32_t)(buf * BTILE_B + r * PITCH + c4 * 4) * 4,
                  Bm + (size_t)(n0 + r) * K + k0 + c4 * 8);
        }
    };

    load_tiles(0, 0);  cp_commit();
    if (64 < K) load_tiles(64, 1);
    cp_commit();

    int buf = 0;
    for (int k0 = 0; k0 < K; k0 += 64) {
        cp_wait<1>();        // chunk k0 retired (FIFO; one group may stay in flight)
        __syncthreads();     // visibility + WAR protection
        const uint32_t* Ab = As + buf * ATILE_B;
        const uint32_t* Bb = Bs + buf * BTILE_B;
#pragma unroll
        for (int ks = 0; ks < 4; ks++) {       // each ks = k16 = 8 u32
            uint32_t afr[4][4];
#pragma unroll
            for (int mf = 0; mf < 4; mf++) {
                const uint32_t* p = Ab + (wm0 + mf * 16 + g) * PITCH + ks * 8 + t4;
                afr[mf][0] = p[0];
                afr[mf][1] = p[8 * PITCH];
                afr[mf][2] = p[4];
                afr[mf][3] = p[8 * PITCH + 4];
            }
            uint32_t bfr[8][2];
#pragma unroll
            for (int nf = 0; nf < 8; nf++) {
                const uint32_t* p = Bb + (wn0 + nf * 8 + g) * PITCH + ks * 8 + t4;
                bfr[nf][0] = p[0];
                bfr[nf][1] = p[4];
            }
#pragma unroll
            for (int mf = 0; mf < 4; mf++)
#pragma unroll
                for (int nf = 0; nf < 8; nf++)
                    mma_f16(acc[mf][nf], afr[mf], bfr[nf]);
        }
        if (k0 + 128 < K) load_tiles(k0 + 128, (buf + 2) % NSTAGE);
        cp_commit();         // commit every iter keeps FIFO accounting exact
        buf = (buf + 1) % NSTAGE;
    }

    // ---- epilogue: fp32 + bias ----
#pragma unroll
    for (int mf = 0; mf < 4; mf++) {
#pragma unroll
        for (int nf = 0; nf < 8; nf++) {
            int nbase = n0 + wn0 + nf * 8 + t4 * 2;
            float bias0 = bias ? bias[nbase]     : 0.f;
            float bias1 = bias ? bias[nbase + 1] : 0.f;
#pragma unroll
            for (int e = 0; e < 4; e++) {
                int m = m0 + wm0 + mf * 16 + g + ((e >= 2) ? 8 : 0);
                int n = nbase + (e & 1);
                C[(size_t)m * ldc + n] = acc[mf][nf][e] + ((e & 1) ? bias1 : bias0);
            }
        }
    }
}

// ---------------- 3-stage pipelined 128x128 fp16 NT GEMM (h0 / preds) -------
// mode 0: C[m*ldc+n] fp32 (+ optional fp16 copy Ch). mode 1: preds remap.
__global__ __launch_bounds__(256, 2) void gemm_f16_p3(
    const __half* __restrict__ A, const __half* __restrict__ Bm,
    const float* __restrict__ bias, float* __restrict__ C,
    __half* __restrict__ Ch,
    int M, int N, int K, int ldc, int mode)
{
    extern __shared__ uint32_t sm[];
    uint32_t* As = sm;
    uint32_t* Bs = sm + NSTAGE * ATILE;
    uint32_t as_u = (uint32_t)__cvta_generic_to_shared(As);
    uint32_t bs_u = (uint32_t)__cvta_generic_to_shared(Bs);

    const int tid = threadIdx.x, lane = tid & 31, warp = tid >> 5;
    const int g = lane >> 2, t4 = lane & 3;
    const int m0 = blockIdx.y * 128, n0 = blockIdx.x * 128;
    const int wm0 = (warp >> 2) * 64, wn0 = (warp & 3) * 32;

    float acc[4][4][4];
#pragma unroll
    for (int mf = 0; mf < 4; mf++)
#pragma unroll
        for (int nf = 0; nf < 4; nf++)
#pragma unroll
            for (int e = 0; e < 4; e++) acc[mf][nf][e] = 0.f;

    auto load_tiles = [&](int k0, int buf) {
#pragma unroll
        for (int it = 0; it < 4; it++) {
            int idx = tid + it * 256;
            int r = idx >> 3, c4 = idx & 7;
            cpa16(as_u + (uint32_t)(buf * ATILE + r * PITCH + c4 * 4) * 4,
                  A + (size_t)(m0 + r) * K + k0 + c4 * 8);
            int gn = n0 + r;
            if (gn < N) {
                cpa16(bs_u + (uint32_t)(buf * ATILE + r * PITCH + c4 * 4) * 4,
                      Bm + (size_t)gn * K + k0 + c4 * 8);
            } else {
                uint4 z = make_uint4(0u, 0u, 0u, 0u);
                *reinterpret_cast<uint4*>(&Bs[buf * ATILE + r * PITCH + c4 * 4]) = z;
            }
        }
    };

    load_tiles(0, 0);  cp_commit();
    if (64 < K) load_tiles(64, 1);
    cp_commit();

    int buf = 0;
    for (int k0 = 0; k0 < K; k0 += 64) {
        cp_wait<1>();
        __syncthreads();
        const uint32_t* Ab = As + buf * ATILE;
        const uint32_t* Bb = Bs + buf * ATILE;
#pragma unroll
        for (int ks = 0; ks < 4; ks++) {
            uint32_t afr[4][4];
#pragma unroll
            for (int mf = 0; mf < 4; mf++) {
                const uint32_t* p = Ab + (wm0 + mf * 16 + g) * PITCH + ks * 8 + t4;
                afr[mf][0] = p[0];
                afr[mf][1] = p[8 * PITCH];
                afr[mf][2] = p[4];
                afr[mf][3] = p[8 * PITCH + 4];
            }
            uint32_t bfr[4][2];
#pragma unroll
            for (int nf = 0; nf < 4; nf++) {
                const uint32_t* p = Bb + (wn0 + nf * 8 + g) * PITCH + ks * 8 + t4;
                bfr[nf][0] = p[0];
                bfr[nf][1] = p[4];
            }
#pragma unroll
            for (int mf = 0; mf < 4; mf++)
#pragma unroll
                for (int nf = 0; nf < 4; nf++)
                    mma_f16(acc[mf][nf], afr[mf], bfr[nf]);
        }
        if (k0 + 128 < K) load_tiles(k0 + 128, (buf + 2) % NSTAGE);
        cp_commit();
        buf = (buf + 1) % NSTAGE;
    }

#pragma unroll
    for (int mf = 0; mf < 4; mf++) {
#pragma unroll
        for (int nf = 0; nf < 4; nf++) {
            int nbase = n0 + wn0 + nf * 8 + t4 * 2;
            float bias0 = 0.f, bias1 = 0.f;
            if (bias) {
                if (nbase < N)     bias0 = bias[nbase];
                if (nbase + 1 < N) bias1 = bias[nbase + 1];
            }
#pragma unroll
            for (int e = 0; e < 4; e++) {
                int m = m0 + wm0 + mf * 16 + g + ((e >= 2) ? 8 : 0);
                int n = nbase + (e & 1);
                if (n >= N) continue;
                float v = acc[mf][nf][e] + ((e & 1) ? bias1 : bias0);
                if (mode == 0) {
                    C[(size_t)m * ldc + n] = v;
                    if (Ch) Ch[(size_t)m * ldc + n] = __float2half_rn(v);
                } else {
                    int t = m >> 13, b = m & (BSZ - 1);
                    C[((size_t)b * T_STEPS + t) * VOCAB + n] = v;
                }
            }
        }
    }
}

// ---------------- gate kernel: h_t = GRU(G[tok], gh, h_prev), dual write ----
__global__ __launch_bounds__(256) void gate_kernel(int t)
{
    int idx = blockIdx.x * blockDim.x + threadIdx.x;
    if (idx >= BSZ * (HIDDEN / 4)) return;
    int m = idx >> 7;
    int n = (idx & 127) * 4;

    const float* hp = (t == 0) ? g_h0 : (g_hs + (size_t)(t - 1) * BSZ * HIDDEN);
    float*  hout  = g_hs  + (size_t)t * BSZ * HIDDEN;
    __half* houth = g_hsh + (size_t)t * BSZ * HIDDEN;
    int tok = g_tok[m * T_STEPS + t];

    const float* Gr = g_G  + (size_t)tok * GW;
    const float* gh = g_gh + (size_t)m * GW;

    float4 gir = *reinterpret_cast<const float4*>(&Gr[n]);
    float4 giz = *reinterpret_cast<const float4*>(&Gr[HIDDEN + n]);
    float4 gin = *reinterpret_cast<const float4*>(&Gr[2 * HIDDEN + n]);
    float4 ghr = *reinterpret_cast<const float4*>(&gh[n]);
    float4 ghz = *reinterpret_cast<const float4*>(&gh[HIDDEN + n]);
    float4 ghn = *reinterpret_cast<const float4*>(&gh[2 * HIDDEN + n]);
    float4 hv  = *reinterpret_cast<const float4*>(&hp[(size_t)m * HIDDEN + n]);

    float4 o;
    {
        float r = 1.f / (1.f + expf(-(gir.x + ghr.x)));
        float z = 1.f / (1.f + expf(-(giz.x + ghz.x)));
        float nn = tanhf(gin.x + r * ghn.x);
        o.x = (1.f - z) * nn + z * hv.x;
    }
    {
        float r = 1.f / (1.f + expf(-(gir.y + ghr.y)));
        float z = 1.f / (1.f + expf(-(giz.y + ghz.y)));
        float nn = tanhf(gin.y + r * ghn.y);
        o.y = (1.f - z) * nn + z * hv.y;
    }
    {
        float r = 1.f / (1.f + expf(-(gir.z + ghr.z)));
        float z = 1.f / (1.f + expf(-(giz.z + ghz.z)));
        float nn = tanhf(gin.z + r * ghn.z);
        o.z = (1.f - z) * nn + z * hv.z;
    }
    {
        float r = 1.f / (1.f + expf(-(gir.w + ghr.w)));
        float z = 1.f / (1.f + expf(-(giz.w + ghz.w)));
        float nn = tanhf(gin.w + r * ghn.w);
        o.w = (1.f - z) * nn + z * hv.w;
    }
    *reinterpret_cast<float4*>(&hout[(size_t)m * HIDDEN + n]) = o;
    __half2 p0 = __floats2half2_rn(o.x, o.y);
    __half2 p1 = __floats2half2_rn(o.z, o.w);
    *reinterpret_cast<__half2*>(&houth[(size_t)m * HIDDEN + n])     = p0;
    *reinterpret_cast<__half2*>(&houth[(size_t)m * HIDDEN + n + 2]) = p1;
}

// ---------------- launch ----------------
extern "C" void kernel_launch(void* const* d_in, const int* in_sizes, int n_in,
                              void* d_out, int out_size)
{
    const float* img    = (const float*)d_in[0];
    const void*  text   = d_in[1];
    const float* emb    = (const float*)d_in[2];
    const float* W_proj = (const float*)d_in[3];
    const float* b_proj = (const float*)d_in[4];
    const float* W_ih   = (const float*)d_in[5];
    const float* W_hh   = (const float*)d_in[6];
    const float* b_ih   = (const float*)d_in[7];
    const float* b_hh   = (const float*)d_in[8];
    const float* W_out  = (const float*)d_in[9];
    const float* b_out  = (const float*)d_in[10];
    float* out = (float*)d_out;

    cudaFuncSetAttribute(gemm_f16_p3,
        cudaFuncAttributeMaxDynamicSharedMemorySize, GEMM_SMEM);
    cudaFuncSetAttribute(gemm_f16_big,
        cudaFuncAttributeMaxDynamicSharedMemorySize, BIG_SMEM);

    float  *ph0, *phs, *pgh;
    __half *ph0h, *phsh, *pimgh, *pWprojh, *pWhhh, *pWouth;
    cudaGetSymbolAddress((void**)&ph0,   g_h0);
    cudaGetSymbolAddress((void**)&ph0h,  g_h0h);
    cudaGetSymbolAddress((void**)&phs,   g_hs);
    cudaGetSymbolAddress((void**)&phsh,  g_hsh);
    cudaGetSymbolAddress((void**)&pgh,   g_gh);
    cudaGetSymbolAddress((void**)&pimgh, g_imgh);
    cudaGetSymbolAddress((void**)&pWprojh, g_Wprojh);
    cudaGetSymbolAddress((void**)&pWhhh,   g_Whhh);
    cudaGetSymbolAddress((void**)&pWouth,  g_Wouth);

    // 1) tokens
    detect_dtype_kernel<<<1, 256>>>((const int*)text);
    convert_tok_kernel<<<(T_STEPS * BSZ + 255) / 256, 256>>>(text);

    // 2) pre-convert GEMM operands to fp16 (once)
    cvt_h_kernel<<<(BSZ * 512 + 255) / 256, 256>>>(img, pimgh, BSZ * 512);
    cvt_h_kernel<<<(HIDDEN * 512 + 255) / 256, 256>>>(W_proj, pWprojh, HIDDEN * 512);
    cvt_h_kernel<<<(GW * HIDDEN + 255) / 256, 256>>>(W_hh, pWhhh, GW * HIDDEN);
    cvt_h_kernel<<<(VOCAB * HIDDEN + 255) / 256, 256>>>(W_out, pWouth, VOCAB * HIDDEN);

    // 3) G lookup table (replaces the entire input-projection GEMM)
    build_G_kernel<<<(VOCAB * GW + 255) / 256, 256>>>(emb, W_ih, b_ih);

    // 4) h0 = img @ W_proj^T + b_proj  (fp32 + fp16 copies)
    gemm_f16_p3<<<dim3(HIDDEN / 128, BSZ / 128), 256, GEMM_SMEM>>>(
        pimgh, pWprojh, b_proj, ph0, ph0h, BSZ, HIDDEN, 512, HIDDEN, 0);

    // 5) 14 GRU steps: 256x128 gh GEMM + gate elementwise
    for (int t = 0; t < T_STEPS; t++) {
        const __half* hph = (t == 0) ? ph0h : (phsh + (size_t)(t - 1) * BSZ * HIDDEN);
        gemm_f16_big<<<dim3(GW / 128, BSZ / 256), 256, BIG_SMEM>>>(
            hph, pWhhh, b_hh, pgh, BSZ, GW, HIDDEN, GW);
        gate_kernel<<<(BSZ * (HIDDEN / 4) + 255) / 256, 256>>>(t);
    }

    // 6) preds = hs @ W_out^T + b_out, remapped to [B, T, V]
    gemm_f16_p3<<<dim3(2, (T_STEPS * BSZ) / 128), 256, GEMM_SMEM>>>(
        phsh, pWouth, b_out, out, nullptr, T_STEPS * BSZ, VOCAB, HIDDEN, VOCAB, 1);
}